// round 2
// baseline (speedup 1.0000x reference)
#include <cuda_runtime.h>

#define NTOT 32768
#define DDIM 256
#define KDIM 512
#define FIVED 1280

// Levels 1..15 concatenated: N/2 + N/4 + ... + 1 = N-1 rows of D floats.
__device__ float g_levH[(NTOT - 1) * DDIM];
__device__ float g_levC[(NTOT - 1) * DDIM];
// Gate pre-activation scratch: up to 16384 rows x 1280.
__device__ float g_Z[16384 * FIVED];

__device__ __forceinline__ float sigf(float x) { return 1.0f / (1.0f + __expf(-x)); }

// ---------------------------------------------------------------------------
// GEMM: Z[m, n] = sum_kk X[m, kk] * W[kk, n],  X[m] = concat(Lrow(m), Rrow(m))
// mode 0 (merge): Lrow = 2m of L (stride ls), Rrow = 2m+1 of R (stride rs)
// mode 1 (sum):   a=m>>k, r=m&((1<<k)-1), t=(a<<(k+1))|(1<<k)|r;
//                 Lrow = t-1 (state, stride 512, h at cols [0,256)),
//                 Rrow = (t>>k)-1 (node, stride 256)
// Tiles: 128x128x16, 256 threads, 8x8 micro-tile.
// ---------------------------------------------------------------------------
__global__ void __launch_bounds__(256) gemm_kernel(
    const float* __restrict__ L, int ls,
    const float* __restrict__ R, int rs,
    const float* __restrict__ W,
    float* __restrict__ Z, int M, int mode, int k)
{
    __shared__ float As[16][129];
    __shared__ float Bs[16][128];

    const int bm = blockIdx.y * 128;
    const int bn = blockIdx.x * 128;
    const int tid = threadIdx.x;
    const int tx = tid & 15;
    const int ty = tid >> 4;

    // Per-thread A-load rows: flat = tid + i*256 -> arow = ty + 16*i, acol = tx
    long lOff[8];
    long rOff[8];
    bool vld[8];
    const int mask = (1 << k) - 1;
#pragma unroll
    for (int i = 0; i < 8; i++) {
        int grow = bm + ty + 16 * i;
        vld[i] = (grow < M);
        int g = vld[i] ? grow : 0;
        int lr, rr;
        if (mode == 0) {
            lr = 2 * g;
            rr = 2 * g + 1;
        } else {
            int a = g >> k;
            int r = g & mask;
            int t = (a << (k + 1)) | (1 << k) | r;
            lr = t - 1;
            rr = (t >> k) - 1;
        }
        lOff[i] = (long)lr * ls;
        rOff[i] = (long)rr * rs;
    }

    float acc[8][8];
#pragma unroll
    for (int ii = 0; ii < 8; ii++)
#pragma unroll
        for (int jj = 0; jj < 8; jj++) acc[ii][jj] = 0.0f;

    // B-tile loaders: 256 threads load 16 rows x 128 cols as float4:
    // each row needs 32 float4s -> 2 threads' worth per row with 16 f4 each?
    // Simpler: thread loads one float4 per row-pair mapping:
    // flat f4 index = tid + i*256, i in 0..7 -> covers 2048 f4 = 16*512B? No:
    // 16 rows * 32 f4 = 512 f4 total -> 2 iterations of 256 threads.
    const int f4col = tid & 31;        // 0..31  (x4 floats = 128 cols)
    const int brow0 = tid >> 5;        // 0..7

    for (int kt = 0; kt < KDIM / 16; kt++) {
        const int k0 = kt * 16;
        const bool leftSide = (k0 < 256);
        const int kc = leftSide ? (k0 + tx) : (k0 - 256 + tx);

#pragma unroll
        for (int i = 0; i < 8; i++) {
            float v = 0.0f;
            if (vld[i]) v = leftSide ? L[lOff[i] + kc] : R[rOff[i] + kc];
            As[tx][ty + 16 * i] = v;
        }
#pragma unroll
        for (int i = 0; i < 2; i++) {
            int br = brow0 + 8 * i;
            const float4 w4 = *(const float4*)&W[(size_t)(k0 + br) * FIVED + bn + f4col * 4];
            *(float4*)&Bs[br][f4col * 4] = w4;
        }
        __syncthreads();

#pragma unroll
        for (int kk = 0; kk < 16; kk++) {
            float af[8], bf[8];
#pragma unroll
            for (int ii = 0; ii < 8; ii++) af[ii] = As[kk][ty + 16 * ii];
#pragma unroll
            for (int jj = 0; jj < 8; jj++) bf[jj] = Bs[kk][tx + 16 * jj];
#pragma unroll
            for (int ii = 0; ii < 8; ii++)
#pragma unroll
                for (int jj = 0; jj < 8; jj++) acc[ii][jj] = fmaf(af[ii], bf[jj], acc[ii][jj]);
        }
        __syncthreads();
    }

#pragma unroll
    for (int ii = 0; ii < 8; ii++) {
        int grow = bm + ty + 16 * ii;
        if (grow < M) {
            float* zr = Z + (size_t)grow * FIVED + bn;
#pragma unroll
            for (int jj = 0; jj < 8; jj++) zr[tx + 16 * jj] = acc[ii][jj];
        }
    }
}

// ---------------------------------------------------------------------------
// Pointwise merge cell: level build. One block per output row, 256 threads.
// ---------------------------------------------------------------------------
__global__ void pw_merge(const float* __restrict__ Z, const float* __restrict__ b,
                         const float* __restrict__ prevC,
                         float* __restrict__ curH, float* __restrict__ curC)
{
    const int m = blockIdx.x;
    const int j = threadIdx.x;
    const float* z = Z + (size_t)m * FIVED;
    float gi = z[j] + b[j];
    float go = z[256 + j] + b[256 + j];
    float gu = z[512 + j] + b[512 + j];
    float gfl = z[768 + j] + b[768 + j];
    float gfr = z[1024 + j] + b[1024 + j];
    float cl = prevC[(size_t)(2 * m) * DDIM + j];
    float cr = prevC[(size_t)(2 * m + 1) * DDIM + j];
    float c = sigf(gi) * tanhf(gu) + sigf(gfl) * cl + sigf(gfr) * cr;
    float h = sigf(go) * tanhf(c);
    curH[(size_t)m * DDIM + j] = h;
    curC[(size_t)m * DDIM + j] = c;
}

// ---------------------------------------------------------------------------
// Pointwise fenwick-step cell. One block per active row m (bit k set).
// r == 0  -> first set bit: state := node  (copy)
// r != 0  -> state := cell(state, node) using Z gates
// State lives directly in d_out: row t-1 = [h (256) | c (256)].
// ---------------------------------------------------------------------------
__global__ void pw_sum(const float* __restrict__ Z, const float* __restrict__ b,
                       const float* __restrict__ nodeH, const float* __restrict__ nodeC,
                       float* __restrict__ out, int k)
{
    const int m = blockIdx.x;
    const int j = threadIdx.x;
    const int mask = (1 << k) - 1;
    const int a = m >> k;
    const int r = m & mask;
    const int t = (a << (k + 1)) | (1 << k) | r;
    const int row = t - 1;
    const int idx = (t >> k) - 1;

    float h, c;
    if (r == 0) {
        h = nodeH[(size_t)idx * DDIM + j];
        c = nodeC[(size_t)idx * DDIM + j];
    } else {
        const float* z = Z + (size_t)m * FIVED;
        float gi = z[j] + b[j];
        float go = z[256 + j] + b[256 + j];
        float gu = z[512 + j] + b[512 + j];
        float gfl = z[768 + j] + b[768 + j];
        float gfr = z[1024 + j] + b[1024 + j];
        float cl = out[(size_t)row * 512 + 256 + j];       // state_c (old)
        float cr = nodeC[(size_t)idx * DDIM + j];
        c = sigf(gi) * tanhf(gu) + sigf(gfl) * cl + sigf(gfr) * cr;
        h = sigf(go) * tanhf(c);
    }
    out[(size_t)row * 512 + j] = h;
    out[(size_t)row * 512 + 256 + j] = c;
}

// Storage offset (in rows) of level k (k>=1) inside g_levH/g_levC.
static inline int lev_off(int k) { return NTOT - (NTOT >> (k - 1)); }

extern "C" void kernel_launch(void* const* d_in, const int* in_sizes, int n_in,
                              void* d_out, int out_size)
{
    const float* h_bot = (const float*)d_in[0];
    const float* c_bot = (const float*)d_in[1];
    const float* W_merge = (const float*)d_in[2];
    const float* b_merge = (const float*)d_in[3];
    const float* W_sum = (const float*)d_in[4];
    const float* b_sum = (const float*)d_in[5];
    float* out = (float*)d_out;

    float *levH, *levC, *Z;
    cudaGetSymbolAddress((void**)&levH, g_levH);
    cudaGetSymbolAddress((void**)&levC, g_levC);
    cudaGetSymbolAddress((void**)&Z, g_Z);

    // ---- Phase 1: build levels 1..15 (merge cells) ----
    for (int k = 1; k <= 15; k++) {
        int Mrows = NTOT >> k;
        const float* prevH = (k == 1) ? h_bot : (levH + (size_t)lev_off(k - 1) * DDIM);
        const float* prevC = (k == 1) ? c_bot : (levC + (size_t)lev_off(k - 1) * DDIM);
        float* curH = levH + (size_t)lev_off(k) * DDIM;
        float* curC = levC + (size_t)lev_off(k) * DDIM;

        dim3 grid(FIVED / 128, (Mrows + 127) / 128);
        gemm_kernel<<<grid, 256>>>(prevH, DDIM, prevH, DDIM, W_merge, Z, Mrows, 0, 0);
        pw_merge<<<Mrows, 256>>>(Z, b_merge, prevC, curH, curC);
    }

    // ---- Phase 2: fenwick prefix combine, k = 0..15 ----
    // k = 0: all active rows have r==0 -> pure copies from level 0 (inputs).
    pw_sum<<<NTOT / 2, 256>>>(Z, b_sum, h_bot, c_bot, out, 0);

    for (int k = 1; k <= 14; k++) {
        const float* nodeH = levH + (size_t)lev_off(k) * DDIM;
        const float* nodeC = levC + (size_t)lev_off(k) * DDIM;
        dim3 grid(FIVED / 128, (NTOT / 2 + 127) / 128);
        gemm_kernel<<<grid, 256>>>(out, 512, nodeH, DDIM, W_sum, Z, NTOT / 2, 1, k);
        pw_sum<<<NTOT / 2, 256>>>(Z, b_sum, nodeH, nodeC, out, k);
    }

    // k = 15: single row t = 32768, r == 0 -> copy from level 15.
    {
        const float* nodeH = levH + (size_t)lev_off(15) * DDIM;
        const float* nodeC = levC + (size_t)lev_off(15) * DDIM;
        pw_sum<<<1, 256>>>(Z, b_sum, nodeH, nodeC, out, 15);
    }
}

// round 9
// speedup vs baseline: 2.3805x; 2.3805x over previous
#include <cuda_runtime.h>
#include <cuda_bf16.h>
#include <cstdint>

#define NTOT 32768
#define DDIM 256
#define KDIM 512
#define FIVED 1280

// ---------------- device scratch ----------------
__device__ float g_levH[(NTOT - 1) * DDIM];
__device__ float g_levC[(NTOT - 1) * DDIM];
__device__ float g_Z[16384 * FIVED];
__device__ __nv_bfloat16 g_WtHiM[FIVED * KDIM];
__device__ __nv_bfloat16 g_WtLoM[FIVED * KDIM];
__device__ __nv_bfloat16 g_WtHiS[FIVED * KDIM];
__device__ __nv_bfloat16 g_WtLoS[FIVED * KDIM];

__device__ __forceinline__ float sigf(float x) { return 1.0f / (1.0f + __expf(-x)); }

// ---------------------------------------------------------------------------
// Weight transpose + bf16 hi/lo split: W[512,1280] -> WtHi/WtLo[1280,512]
// ---------------------------------------------------------------------------
__global__ void transpose_w(const float* __restrict__ W,
                            __nv_bfloat16* __restrict__ WtHi,
                            __nv_bfloat16* __restrict__ WtLo) {
    __shared__ float t[32][33];
    int bx = blockIdx.x * 32;   // n
    int by = blockIdx.y * 32;   // k
    int x = threadIdx.x, y = threadIdx.y;
#pragma unroll
    for (int i = 0; i < 32; i += 8)
        t[y + i][x] = W[(size_t)(by + y + i) * FIVED + bx + x];
    __syncthreads();
#pragma unroll
    for (int i = 0; i < 32; i += 8) {
        float v = t[x][y + i];
        __nv_bfloat16 hi = __float2bfloat16(v);
        __nv_bfloat16 lo = __float2bfloat16(v - __bfloat162float(hi));
        WtHi[(size_t)(bx + y + i) * KDIM + by + x] = hi;
        WtLo[(size_t)(bx + y + i) * KDIM + by + x] = lo;
    }
}

// ---------------- mma.sync helpers ----------------
__device__ __forceinline__ uint32_t smem_addr(const void* p) {
    return (uint32_t)__cvta_generic_to_shared(p);
}
__device__ __forceinline__ void ldm_x4(uint32_t r[4], uint32_t addr) {
    asm volatile("ldmatrix.sync.aligned.m8n8.x4.shared.b16 {%0,%1,%2,%3}, [%4];"
                 : "=r"(r[0]), "=r"(r[1]), "=r"(r[2]), "=r"(r[3]) : "r"(addr));
}
__device__ __forceinline__ void mma16816(float d[4], const uint32_t a[4],
                                         uint32_t b0, uint32_t b1) {
    asm volatile(
        "mma.sync.aligned.m16n8k16.row.col.f32.bf16.bf16.f32 "
        "{%0,%1,%2,%3}, {%4,%5,%6,%7}, {%8,%9}, {%0,%1,%2,%3};"
        : "+f"(d[0]), "+f"(d[1]), "+f"(d[2]), "+f"(d[3])
        : "r"(a[0]), "r"(a[1]), "r"(a[2]), "r"(a[3]), "r"(b0), "r"(b1));
}

// SMEM row stride in bf16 elements (32 data + 8 pad = 80B rows; 16B aligned)
#define ROWE 40

// ---------------------------------------------------------------------------
// GEMM: Z[m, 0:1280] = concat(Lrow(m), Rrow(m)) @ W  via bf16x3 mma.sync
// mode 0 (merge): Lrow = 2m (stride ls), Rrow = 2m+1 (stride rs)
// mode 1 (sum):   a=m>>k, r=m&((1<<k)-1), t=(a<<(k+1))|(1<<k)|r;
//                 Lrow = t-1 (stride 512), Rrow = (t>>k)-1 (stride 256)
// CTA tile 128x128, 8 warps (4M x 2N), warp tile 32x64, K chunks of 32.
// ---------------------------------------------------------------------------
__global__ void __launch_bounds__(256, 1) mma_gemm(
    const float* __restrict__ L, int ls,
    const float* __restrict__ R, int rs,
    const __nv_bfloat16* __restrict__ WtHi,
    const __nv_bfloat16* __restrict__ WtLo,
    float* __restrict__ Z, int M, int mode, int k)
{
    __shared__ __align__(16) __nv_bfloat16 Ah[128 * ROWE];
    __shared__ __align__(16) __nv_bfloat16 Al[128 * ROWE];
    __shared__ __align__(16) __nv_bfloat16 Bh[128 * ROWE];
    __shared__ __align__(16) __nv_bfloat16 Bl[128 * ROWE];

    const int tid = threadIdx.x;
    const int wid = tid >> 5;
    const int lane = tid & 31;
    const int warpM = wid & 3;        // 0..3  -> 32-row slice
    const int warpN = wid >> 2;       // 0..1  -> 64-col slice
    const int bm = blockIdx.y * 128;
    const int bn = blockIdx.x * 128;

    // ---- load geometry: one row per thread-pair, 16 K-elems per thread ----
    const int row2 = tid >> 1;        // 0..127
    const int half = tid & 1;
    int g = bm + row2;
    if (g >= M) g = 0;
    int lr, rr;
    const int mask = (1 << k) - 1;
    if (mode == 0) { lr = 2 * g; rr = 2 * g + 1; }
    else {
        int a = g >> k;
        int r = g & mask;
        int t = (a << (k + 1)) | (1 << k) | r;
        lr = t - 1;
        rr = (t >> k) - 1;
    }
    const float* Lrow = L + (size_t)lr * ls + half * 16;
    const float* Rrow = R + (size_t)rr * rs + half * 16;
    const size_t bRow = (size_t)(bn + row2) * KDIM + half * 16;
    __nv_bfloat16* aDstH = Ah + row2 * ROWE + half * 16;
    __nv_bfloat16* aDstL = Al + row2 * ROWE + half * 16;
    __nv_bfloat16* bDstH = Bh + row2 * ROWE + half * 16;
    __nv_bfloat16* bDstL = Bl + row2 * ROWE + half * 16;

    // ---- ldmatrix source addresses (per-lane) ----
    // A m-frag: rows warpM*32 + mf*16 + (lane&15), kcol kk + ((lane>>4)<<3)
    const int aRowL = warpM * 32 + (lane & 15);
    const int aKL = (lane >> 4) << 3;
    // B nf-pair: rows warpN*64 + nfp*16 + ((lane>>4)<<3) + (lane&7),
    //            kcol kk + ((lane>>3)&1)*8
    const int bRowL = warpN * 64 + ((lane >> 4) << 3) + (lane & 7);
    const int bKL = ((lane >> 3) & 1) << 3;

    float acc[2][8][4];
#pragma unroll
    for (int mf = 0; mf < 2; mf++)
#pragma unroll
        for (int nf = 0; nf < 8; nf++)
#pragma unroll
            for (int j = 0; j < 4; j++) acc[mf][nf][j] = 0.0f;

#pragma unroll 1
    for (int c = 0; c < 16; c++) {
        const int k0 = c * 32;

        // ---- A fill: 16 f32 -> hi/lo bf16 ----
        {
            const float* ap = (k0 < 256) ? (Lrow + k0) : (Rrow + (k0 - 256));
            uint32_t hw[8], lw[8];
#pragma unroll
            for (int j = 0; j < 4; j++) {
                float4 u = *(const float4*)(ap + j * 4);
                __nv_bfloat16 h0 = __float2bfloat16(u.x);
                __nv_bfloat16 h1 = __float2bfloat16(u.y);
                __nv_bfloat16 h2 = __float2bfloat16(u.z);
                __nv_bfloat16 h3 = __float2bfloat16(u.w);
                __nv_bfloat16 l0 = __float2bfloat16(u.x - __bfloat162float(h0));
                __nv_bfloat16 l1 = __float2bfloat16(u.y - __bfloat162float(h1));
                __nv_bfloat16 l2 = __float2bfloat16(u.z - __bfloat162float(h2));
                __nv_bfloat16 l3 = __float2bfloat16(u.w - __bfloat162float(h3));
                __nv_bfloat162 p0; p0.x = h0; p0.y = h1;
                __nv_bfloat162 p1; p1.x = h2; p1.y = h3;
                __nv_bfloat162 q0; q0.x = l0; q0.y = l1;
                __nv_bfloat162 q1; q1.x = l2; q1.y = l3;
                hw[2 * j] = *(uint32_t*)&p0;
                hw[2 * j + 1] = *(uint32_t*)&p1;
                lw[2 * j] = *(uint32_t*)&q0;
                lw[2 * j + 1] = *(uint32_t*)&q1;
            }
            *(uint4*)(aDstH) = make_uint4(hw[0], hw[1], hw[2], hw[3]);
            *(uint4*)(aDstH + 8) = make_uint4(hw[4], hw[5], hw[6], hw[7]);
            *(uint4*)(aDstL) = make_uint4(lw[0], lw[1], lw[2], lw[3]);
            *(uint4*)(aDstL + 8) = make_uint4(lw[4], lw[5], lw[6], lw[7]);
        }
        // ---- B fill: preconverted bf16 rows ----
        {
            const uint4* bh = (const uint4*)(WtHi + bRow + k0);
            const uint4* bl = (const uint4*)(WtLo + bRow + k0);
            *(uint4*)(bDstH) = bh[0];
            *(uint4*)(bDstH + 8) = bh[1];
            *(uint4*)(bDstL) = bl[0];
            *(uint4*)(bDstL + 8) = bl[1];
        }
        __syncthreads();

        // ---- compute: 2 k16 steps ----
#pragma unroll
        for (int kk = 0; kk < 32; kk += 16) {
            uint32_t ah[2][4], al[2][4];
#pragma unroll
            for (int mf = 0; mf < 2; mf++) {
                const int r = aRowL + mf * 16;
                const int kb = kk + aKL;
                ldm_x4(ah[mf], smem_addr(Ah + r * ROWE + kb));
                ldm_x4(al[mf], smem_addr(Al + r * ROWE + kb));
            }
#pragma unroll
            for (int nfp = 0; nfp < 4; nfp++) {
                uint32_t bh[4], bl[4];
                const int nr = bRowL + nfp * 16;
                const int kb = kk + bKL;
                ldm_x4(bh, smem_addr(Bh + nr * ROWE + kb));
                ldm_x4(bl, smem_addr(Bl + nr * ROWE + kb));
#pragma unroll
                for (int mf = 0; mf < 2; mf++) {
#pragma unroll
                    for (int j = 0; j < 2; j++) {
                        float* d = acc[mf][nfp * 2 + j];
                        mma16816(d, ah[mf], bh[2 * j], bh[2 * j + 1]);
                        mma16816(d, ah[mf], bl[2 * j], bl[2 * j + 1]);
                        mma16816(d, al[mf], bh[2 * j], bh[2 * j + 1]);
                    }
                }
            }
        }
        __syncthreads();
    }

    // ---- epilogue: fragment layout (row lane>>2 [+8], col (lane&3)*2 [+1]) ----
#pragma unroll
    for (int mf = 0; mf < 2; mf++) {
        const int r0 = bm + warpM * 32 + mf * 16 + (lane >> 2);
#pragma unroll
        for (int nf = 0; nf < 8; nf++) {
            const int cc = bn + warpN * 64 + nf * 8 + (lane & 3) * 2;
            float* p = Z + (size_t)r0 * FIVED + cc;
            if (r0 < M) {
                p[0] = acc[mf][nf][0];
                p[1] = acc[mf][nf][1];
            }
            if (r0 + 8 < M) {
                float* q = p + 8 * FIVED;
                q[0] = acc[mf][nf][2];
                q[1] = acc[mf][nf][3];
            }
        }
    }
}

// ---------------------------------------------------------------------------
// Pointwise merge cell
// ---------------------------------------------------------------------------
__global__ void pw_merge(const float* __restrict__ Z, const float* __restrict__ b,
                         const float* __restrict__ prevC,
                         float* __restrict__ curH, float* __restrict__ curC)
{
    const int m = blockIdx.x;
    const int j = threadIdx.x;
    const float* z = Z + (size_t)m * FIVED;
    float gi = z[j] + b[j];
    float go = z[256 + j] + b[256 + j];
    float gu = z[512 + j] + b[512 + j];
    float gfl = z[768 + j] + b[768 + j];
    float gfr = z[1024 + j] + b[1024 + j];
    float cl = prevC[(size_t)(2 * m) * DDIM + j];
    float cr = prevC[(size_t)(2 * m + 1) * DDIM + j];
    float c = sigf(gi) * tanhf(gu) + sigf(gfl) * cl + sigf(gfr) * cr;
    float h = sigf(go) * tanhf(c);
    curH[(size_t)m * DDIM + j] = h;
    curC[(size_t)m * DDIM + j] = c;
}

// ---------------------------------------------------------------------------
// Pointwise fenwick-step cell (state lives in d_out rows [h|c])
// ---------------------------------------------------------------------------
__global__ void pw_sum(const float* __restrict__ Z, const float* __restrict__ b,
                       const float* __restrict__ nodeH, const float* __restrict__ nodeC,
                       float* __restrict__ out, int k)
{
    const int m = blockIdx.x;
    const int j = threadIdx.x;
    const int mask = (1 << k) - 1;
    const int a = m >> k;
    const int r = m & mask;
    const int t = (a << (k + 1)) | (1 << k) | r;
    const int row = t - 1;
    const int idx = (t >> k) - 1;

    float h, c;
    if (r == 0) {
        h = nodeH[(size_t)idx * DDIM + j];
        c = nodeC[(size_t)idx * DDIM + j];
    } else {
        const float* z = Z + (size_t)m * FIVED;
        float gi = z[j] + b[j];
        float go = z[256 + j] + b[256 + j];
        float gu = z[512 + j] + b[512 + j];
        float gfl = z[768 + j] + b[768 + j];
        float gfr = z[1024 + j] + b[1024 + j];
        float cl = out[(size_t)row * 512 + 256 + j];
        float cr = nodeC[(size_t)idx * DDIM + j];
        c = sigf(gi) * tanhf(gu) + sigf(gfl) * cl + sigf(gfr) * cr;
        h = sigf(go) * tanhf(c);
    }
    out[(size_t)row * 512 + j] = h;
    out[(size_t)row * 512 + 256 + j] = c;
}

static inline int lev_off(int k) { return NTOT - (NTOT >> (k - 1)); }

extern "C" void kernel_launch(void* const* d_in, const int* in_sizes, int n_in,
                              void* d_out, int out_size)
{
    const float* h_bot = (const float*)d_in[0];
    const float* c_bot = (const float*)d_in[1];
    const float* W_merge = (const float*)d_in[2];
    const float* b_merge = (const float*)d_in[3];
    const float* W_sum = (const float*)d_in[4];
    const float* b_sum = (const float*)d_in[5];
    float* out = (float*)d_out;

    float *levH, *levC, *Z;
    __nv_bfloat16 *WtHiM, *WtLoM, *WtHiS, *WtLoS;
    cudaGetSymbolAddress((void**)&levH, g_levH);
    cudaGetSymbolAddress((void**)&levC, g_levC);
    cudaGetSymbolAddress((void**)&Z, g_Z);
    cudaGetSymbolAddress((void**)&WtHiM, g_WtHiM);
    cudaGetSymbolAddress((void**)&WtLoM, g_WtLoM);
    cudaGetSymbolAddress((void**)&WtHiS, g_WtHiS);
    cudaGetSymbolAddress((void**)&WtLoS, g_WtLoS);

    transpose_w<<<dim3(FIVED / 32, KDIM / 32), dim3(32, 8)>>>(W_merge, WtHiM, WtLoM);
    transpose_w<<<dim3(FIVED / 32, KDIM / 32), dim3(32, 8)>>>(W_sum, WtHiS, WtLoS);

    // ---- Phase 1: build levels 1..15 ----
    for (int k = 1; k <= 15; k++) {
        int Mrows = NTOT >> k;
        const float* prevH = (k == 1) ? h_bot : (levH + (size_t)lev_off(k - 1) * DDIM);
        const float* prevC = (k == 1) ? c_bot : (levC + (size_t)lev_off(k - 1) * DDIM);
        float* curH = levH + (size_t)lev_off(k) * DDIM;
        float* curC = levC + (size_t)lev_off(k) * DDIM;

        dim3 grid(FIVED / 128, (Mrows + 127) / 128);
        mma_gemm<<<grid, 256>>>(prevH, DDIM, prevH, DDIM, WtHiM, WtLoM, Z, Mrows, 0, 0);
        pw_merge<<<Mrows, 256>>>(Z, b_merge, prevC, curH, curC);
    }

    // ---- Phase 2: fenwick prefix combine ----
    pw_sum<<<NTOT / 2, 256>>>(Z, b_sum, h_bot, c_bot, out, 0);

    for (int k = 1; k <= 14; k++) {
        const float* nodeH = levH + (size_t)lev_off(k) * DDIM;
        const float* nodeC = levC + (size_t)lev_off(k) * DDIM;
        dim3 grid(FIVED / 128, (NTOT / 2 + 127) / 128);
        mma_gemm<<<grid, 256>>>(out, 512, nodeH, DDIM, WtHiS, WtLoS, Z, NTOT / 2, 1, k);
        pw_sum<<<NTOT / 2, 256>>>(Z, b_sum, nodeH, nodeC, out, k);
    }

    {
        const float* nodeH = levH + (size_t)lev_off(15) * DDIM;
        const float* nodeC = levC + (size_t)lev_off(15) * DDIM;
        pw_sum<<<1, 256>>>(Z, b_sum, nodeH, nodeC, out, 15);
    }
}